// round 11
// baseline (speedup 1.0000x reference)
#include <cuda_runtime.h>

#define HID 128
#define LAT 256
#define NN  1024
#define GRIDP 128u
#define NT   512

// ---------------- scratch (no allocations allowed) ----------------
__device__ float d_gvec[HID];
__device__ float d_w1hT[HID * HID];
__device__ float d_w2T [HID * HID];
__device__ float d_WaT [HID * HID];
__device__ float d_WbT [HID * HID];
__device__ float d_piT [HID * NN];
__device__ float d_pbT [HID * NN];

__device__ unsigned d_bar_count = 0;
__device__ unsigned d_bar_gen   = 0;

// CG-style grid barrier (proven correct): 128 co-resident blocks.
__device__ __forceinline__ void grid_bar() {
    __syncthreads();
    if (threadIdx.x == 0) {
        unsigned g;
        asm volatile("ld.acquire.gpu.global.u32 %0, [%1];"
                     : "=r"(g) : "l"(&d_bar_gen) : "memory");
        unsigned old, one = 1u, zero = 0u;
        asm volatile("atom.release.gpu.global.add.u32 %0, [%1], %2;"
                     : "=r"(old) : "l"(&d_bar_count), "r"(one) : "memory");
        if (old == GRIDP - 1u) {
            asm volatile("st.relaxed.gpu.global.u32 [%0], %1;"
                         :: "l"(&d_bar_count), "r"(zero) : "memory");
            asm volatile("red.release.gpu.global.add.u32 [%0], %1;"
                         :: "l"(&d_bar_gen), "r"(one) : "memory");
        } else {
            unsigned cur;
            do {
                asm volatile("ld.acquire.gpu.global.u32 %0, [%1];"
                             : "=r"(cur) : "l"(&d_bar_gen) : "memory");
            } while (cur == g);
        }
    }
    __syncthreads();
}

__device__ __forceinline__ float warp_sum(float v) {
#pragma unroll
    for (int o = 16; o; o >>= 1) v += __shfl_xor_sync(0xffffffffu, v, o);
    return v;
}

__device__ __forceinline__ float2 f2add(float2 a, float2 b) {
    unsigned long long ua = *reinterpret_cast<unsigned long long*>(&a);
    unsigned long long ub = *reinterpret_cast<unsigned long long*>(&b);
    unsigned long long ur;
    asm("add.rn.f32x2 %0, %1, %2;" : "=l"(ur) : "l"(ua), "l"(ub));
    return *reinterpret_cast<float2*>(&ur);
}
__device__ __forceinline__ float2 f2fma(float2 a, float2 b, float2 c) {
    unsigned long long ua = *reinterpret_cast<unsigned long long*>(&a);
    unsigned long long ub = *reinterpret_cast<unsigned long long*>(&b);
    unsigned long long uc = *reinterpret_cast<unsigned long long*>(&c);
    unsigned long long ur;
    asm("fma.rn.f32x2 %0, %1, %2, %3;" : "=l"(ur) : "l"(ua), "l"(ub), "l"(uc));
    return *reinterpret_cast<float2*>(&ur);
}
__device__ __forceinline__ float sigm(float x) { return 1.f / (1.f + __expf(-x)); }

// ================= kernel Pre: transposes + latent chain, barrier, node MLP =================
__global__ __launch_bounds__(NT) void kPre(
    const float* __restrict__ z,  const float* __restrict__ ne,
    const float* __restrict__ ld_w1, const float* __restrict__ ld_b1,
    const float* __restrict__ ld_g,  const float* __restrict__ ld_be,
    const float* __restrict__ ld_w2, const float* __restrict__ ld_b2,
    const float* __restrict__ nr_w1, const float* __restrict__ nr_b1,
    const float* __restrict__ nr_g,  const float* __restrict__ nr_be,
    const float* __restrict__ nr_w2, const float* __restrict__ nr_b2,
    const float* __restrict__ em_w1, const float* __restrict__ em_b1)
{
    __shared__ float SM[6528];   // 25.5 KB
    const int t   = threadIdx.x;
    const int blk = blockIdx.x;
    const int w = t >> 5, l = t & 31;

    // ----- phase 0a: weight transposes (blocks 64..127) -----
    if (blk >= 64) {
        float (*s)[33] = (float(*)[33])SM;
        const int tileIdx = blk - 64;
        const int m  = tileIdx >> 4;
        const int t16 = tileIdx & 15;
        const int c0 = (t16 >> 2) * 32;
        const int k0 = (t16 & 3) * 32;
        const float* src; int stride, colOff; float* dst;
        if      (m == 0) { src = nr_w1; stride = LAT; colOff = 0;   dst = d_w1hT; }
        else if (m == 1) { src = nr_w2; stride = HID; colOff = 0;   dst = d_w2T;  }
        else if (m == 2) { src = em_w1; stride = LAT; colOff = 0;   dst = d_WaT;  }
        else             { src = em_w1; stride = LAT; colOff = HID; dst = d_WbT;  }
        const int x = t & 31, y = t >> 5;
#pragma unroll
        for (int yy = y; yy < 32; yy += 16)
            s[yy][x] = src[(k0 + yy) * stride + colOff + c0 + x];
        __syncthreads();
#pragma unroll
        for (int yy = y; yy < 32; yy += 16)
            dst[(c0 + yy) * HID + k0 + x] = s[x][yy];
    }

    // ----- phase 0b: latent chain on block 0 -> d_gvec -----
    if (blk == 0) {
        float* z_s = SM;             // 256
        float* hA  = SM + 256;       // 256
        float* aA  = SM + 512;       // 256
        float* gA  = SM + 768;       // 128
        float* redA = SM + 896;      // 8
        float* redB = SM + 904;      // 8

        if (t < 64) ((float4*)z_s)[t] = ((const float4*)z)[t];
        __syncthreads();
        const float4* zf4 = (const float4*)z_s;

        for (int m0 = 0; m0 < 16; m0 += 4) {
            float p[4];
#pragma unroll
            for (int k = 0; k < 4; k++) {
                int r = (m0 + k) * 16 + w;
                const float4* wr = (const float4*)&ld_w1[r * LAT];
                float4 A = wr[l], B = wr[l + 32];
                float4 za = zf4[l], zb = zf4[l + 32];
                p[k] = A.x*za.x + A.y*za.y + A.z*za.z + A.w*za.w
                     + B.x*zb.x + B.y*zb.y + B.z*zb.z + B.w*zb.w;
            }
#pragma unroll
            for (int o = 16; o; o >>= 1) {
                p[0] += __shfl_xor_sync(0xffffffffu, p[0], o);
                p[1] += __shfl_xor_sync(0xffffffffu, p[1], o);
                p[2] += __shfl_xor_sync(0xffffffffu, p[2], o);
                p[3] += __shfl_xor_sync(0xffffffffu, p[3], o);
            }
            if (l == 0) {
#pragma unroll
                for (int k = 0; k < 4; k++) {
                    int r = (m0 + k) * 16 + w;
                    hA[r] = p[k] + ld_b1[r];
                }
            }
        }
        __syncthreads();

        {
            float x = (t < 256) ? hA[t] : 0.f;
            float s1 = warp_sum(x), s2 = warp_sum(x * x);
            if (l == 0 && w < 8) { redA[w] = s1; redB[w] = s2; }
            __syncthreads();
            float tot = 0.f, tot2 = 0.f;
#pragma unroll
            for (int i = 0; i < 8; i++) { tot += redA[i]; tot2 += redB[i]; }
            float mu = tot * (1.f / 256.f);
            float var = tot2 * (1.f / 256.f) - mu * mu;
            float rs = rsqrtf(var + 1e-5f);
            if (t < 256) aA[t] = fmaxf((x - mu) * rs * ld_g[t] + ld_be[t], 0.f);
        }
        __syncthreads();
        const float4* af4 = (const float4*)aA;

        for (int m0 = 0; m0 < 8; m0 += 4) {
            float p[4];
#pragma unroll
            for (int k = 0; k < 4; k++) {
                int r = (m0 + k) * 16 + w;
                const float4* wr = (const float4*)&ld_w2[r * LAT];
                float4 A = wr[l], B = wr[l + 32];
                float4 za = af4[l], zb = af4[l + 32];
                p[k] = A.x*za.x + A.y*za.y + A.z*za.z + A.w*za.w
                     + B.x*zb.x + B.y*zb.y + B.z*zb.z + B.w*zb.w;
            }
#pragma unroll
            for (int o = 16; o; o >>= 1) {
                p[0] += __shfl_xor_sync(0xffffffffu, p[0], o);
                p[1] += __shfl_xor_sync(0xffffffffu, p[1], o);
                p[2] += __shfl_xor_sync(0xffffffffu, p[2], o);
                p[3] += __shfl_xor_sync(0xffffffffu, p[3], o);
            }
            if (l == 0) {
#pragma unroll
                for (int k = 0; k < 4; k++) {
                    int r = (m0 + k) * 16 + w;
                    gA[r] = p[k] + ld_b2[r];
                }
            }
        }
        __syncthreads();
        const float4* gf4 = (const float4*)gA;

        for (int m0 = 0; m0 < 8; m0 += 4) {
            float p[4];
#pragma unroll
            for (int k = 0; k < 4; k++) {
                int r = (m0 + k) * 16 + w;
                const float4* wr = (const float4*)&nr_w1[r * LAT + HID];
                float4 A = wr[l];
                float4 ga = gf4[l];
                p[k] = A.x*ga.x + A.y*ga.y + A.z*ga.z + A.w*ga.w;
            }
#pragma unroll
            for (int o = 16; o; o >>= 1) {
                p[0] += __shfl_xor_sync(0xffffffffu, p[0], o);
                p[1] += __shfl_xor_sync(0xffffffffu, p[1], o);
                p[2] += __shfl_xor_sync(0xffffffffu, p[2], o);
                p[3] += __shfl_xor_sync(0xffffffffu, p[3], o);
            }
            if (l == 0) {
#pragma unroll
                for (int k = 0; k < 4; k++) {
                    int r = (m0 + k) * 16 + w;
                    d_gvec[r] = p[k] + nr_b1[r];
                }
            }
        }
    }
    grid_bar();   // transposed weights + d_gvec visible everywhere

    // ----- phase B: node MLP -> piT / pbT (all 128 blocks, 8 nodes each) -----
    {
        float* A  = SM;              // 1024: ne, later nf
        float* B  = SM + 1024;       // 1024: h1/LN, later pi
        float* WT = SM + 2048;       // 4096: weight tile [32][128]
        float* red1 = SM + 6144;     // 16
        float* red2 = SM + 6160;     // 16
        const int i0 = blk * 8;
        const int r  = t >> 6;       // node 0..7
        const int u  = t & 63;
        const int j2 = u * 2;
        const int wh2 = u >> 5;
        const int ti8 = t * 8;

        __syncthreads();             // SM reuse after phase 0
        for (int q = t; q < 8 * HID; q += NT) A[q] = ne[i0 * HID + q];
        __syncthreads();

        // GEMV1: h1 = ne @ w1hT + gvec
        float2 acc = *(const float2*)&d_gvec[j2];
#pragma unroll
        for (int ct = 0; ct < 4; ct++) {
            *(float4*)&WT[ti8]     = *(const float4*)&d_w1hT[ct * 4096 + ti8];
            *(float4*)&WT[ti8 + 4] = *(const float4*)&d_w1hT[ct * 4096 + ti8 + 4];
            __syncthreads();
#pragma unroll
            for (int c4 = 0; c4 < 32; c4 += 4) {
                float4 nv = *(const float4*)&A[r * HID + ct * 32 + c4];
                acc = f2fma(make_float2(nv.x, nv.x), *(const float2*)&WT[(c4 + 0) * HID + j2], acc);
                acc = f2fma(make_float2(nv.y, nv.y), *(const float2*)&WT[(c4 + 1) * HID + j2], acc);
                acc = f2fma(make_float2(nv.z, nv.z), *(const float2*)&WT[(c4 + 2) * HID + j2], acc);
                acc = f2fma(make_float2(nv.w, nv.w), *(const float2*)&WT[(c4 + 3) * HID + j2], acc);
            }
            __syncthreads();
        }
        *(float2*)&B[r * HID + j2] = acc;
        __syncthreads();

        // LayerNorm(128) + relu
        {
            float x0 = B[r * HID + u], x1 = B[r * HID + u + 64];
            float s1 = warp_sum(x0 + x1);
            float s2 = warp_sum(x0 * x0 + x1 * x1);
            if (l == 0) { red1[r * 2 + wh2] = s1; red2[r * 2 + wh2] = s2; }
            __syncthreads();
            float mu  = (red1[r * 2] + red1[r * 2 + 1]) * (1.f / 128.f);
            float var = (red2[r * 2] + red2[r * 2 + 1]) * (1.f / 128.f) - mu * mu;
            float rs = rsqrtf(var + 1e-5f);
            B[r * HID + u]      = fmaxf((x0 - mu) * rs * nr_g[u]      + nr_be[u],      0.f);
            B[r * HID + u + 64] = fmaxf((x1 - mu) * rs * nr_g[u + 64] + nr_be[u + 64], 0.f);
        }
        __syncthreads();

        // GEMV2: nf = a @ w2T + b2 -> A
        float2 nf = *(const float2*)&nr_b2[j2];
#pragma unroll
        for (int ct = 0; ct < 4; ct++) {
            *(float4*)&WT[ti8]     = *(const float4*)&d_w2T[ct * 4096 + ti8];
            *(float4*)&WT[ti8 + 4] = *(const float4*)&d_w2T[ct * 4096 + ti8 + 4];
            __syncthreads();
#pragma unroll
            for (int c4 = 0; c4 < 32; c4 += 4) {
                float4 av = *(const float4*)&B[r * HID + ct * 32 + c4];
                nf = f2fma(make_float2(av.x, av.x), *(const float2*)&WT[(c4 + 0) * HID + j2], nf);
                nf = f2fma(make_float2(av.y, av.y), *(const float2*)&WT[(c4 + 1) * HID + j2], nf);
                nf = f2fma(make_float2(av.z, av.z), *(const float2*)&WT[(c4 + 2) * HID + j2], nf);
                nf = f2fma(make_float2(av.w, av.w), *(const float2*)&WT[(c4 + 3) * HID + j2], nf);
            }
            __syncthreads();
        }
        *(float2*)&A[r * HID + j2] = nf;
        __syncthreads();

        // GEMV3: pi = nf @ WaT -> B
        float2 pi = make_float2(0.f, 0.f);
#pragma unroll
        for (int ct = 0; ct < 4; ct++) {
            *(float4*)&WT[ti8]     = *(const float4*)&d_WaT[ct * 4096 + ti8];
            *(float4*)&WT[ti8 + 4] = *(const float4*)&d_WaT[ct * 4096 + ti8 + 4];
            __syncthreads();
#pragma unroll
            for (int c4 = 0; c4 < 32; c4 += 4) {
                float4 fv = *(const float4*)&A[r * HID + ct * 32 + c4];
                pi = f2fma(make_float2(fv.x, fv.x), *(const float2*)&WT[(c4 + 0) * HID + j2], pi);
                pi = f2fma(make_float2(fv.y, fv.y), *(const float2*)&WT[(c4 + 1) * HID + j2], pi);
                pi = f2fma(make_float2(fv.z, fv.z), *(const float2*)&WT[(c4 + 2) * HID + j2], pi);
                pi = f2fma(make_float2(fv.w, fv.w), *(const float2*)&WT[(c4 + 3) * HID + j2], pi);
            }
            __syncthreads();
        }
        *(float2*)&B[r * HID + j2] = pi;

        // GEMV4: pb = nf @ WbT + em_b1 -> park in WT
        float2 pb = *(const float2*)&em_b1[j2];
#pragma unroll
        for (int ct = 0; ct < 4; ct++) {
            __syncthreads();
            *(float4*)&WT[ti8]     = *(const float4*)&d_WbT[ct * 4096 + ti8];
            *(float4*)&WT[ti8 + 4] = *(const float4*)&d_WbT[ct * 4096 + ti8 + 4];
            __syncthreads();
#pragma unroll
            for (int c4 = 0; c4 < 32; c4 += 4) {
                float4 fv = *(const float4*)&A[r * HID + ct * 32 + c4];
                pb = f2fma(make_float2(fv.x, fv.x), *(const float2*)&WT[(c4 + 0) * HID + j2], pb);
                pb = f2fma(make_float2(fv.y, fv.y), *(const float2*)&WT[(c4 + 1) * HID + j2], pb);
                pb = f2fma(make_float2(fv.z, fv.z), *(const float2*)&WT[(c4 + 2) * HID + j2], pb);
                pb = f2fma(make_float2(fv.w, fv.w), *(const float2*)&WT[(c4 + 3) * HID + j2], pb);
            }
        }
        __syncthreads();
        *(float2*)&WT[r * HID + j2] = pb;
        __syncthreads();

        if (t < HID) {
            const int j = t;
            float4 lo = make_float4(B[0*HID+j], B[1*HID+j], B[2*HID+j], B[3*HID+j]);
            float4 hi = make_float4(B[4*HID+j], B[5*HID+j], B[6*HID+j], B[7*HID+j]);
            *(float4*)&d_piT[j * NN + i0]     = lo;
            *(float4*)&d_piT[j * NN + i0 + 4] = hi;
            float4 lo2 = make_float4(WT[0*HID+j], WT[1*HID+j], WT[2*HID+j], WT[3*HID+j]);
            float4 hi2 = make_float4(WT[4*HID+j], WT[5*HID+j], WT[6*HID+j], WT[7*HID+j]);
            *(float4*)&d_pbT[j * NN + i0]     = lo2;
            *(float4*)&d_pbT[j * NN + i0 + 4] = hi2;
        }
    }
}

// ================= kernel C: edge scores + fused symmetrize (136 pair-tiles) =================
__global__ __launch_bounds__(NT) void kC(
    const float* __restrict__ em_w2, const float* __restrict__ em_b2,
    float* __restrict__ out)
{
    __shared__ float SM[8448];
    float* pool = SM;
    float* w_s  = SM + 8192;
    float (*piI)[64] = (float(*)[64])(pool);
    float (*pbJ)[64] = (float(*)[64])(pool + 2048);
    float (*piJ)[64] = (float(*)[64])(pool + 4096);
    float (*pbI)[64] = (float(*)[64])(pool + 6144);

    const int t = threadIdx.x;
    const int tx = t & 31;
    const int ty = t >> 5;
    const int ty4 = ty * 4;

    int b = blockIdx.x, bi = 0;
    while (b >= (16 - bi)) { b -= (16 - bi); bi++; }
    const int bj = bi + b;
    const int i0 = bi * 64, j0 = bj * 64;

    if (t < HID) w_s[t] = em_w2[t];

    float2 acc1[4] = {};
    float2 acc2[4] = {};

#pragma unroll
    for (int ch = 0; ch < 4; ch++) {
        __syncthreads();
        const int h0 = ch * 32;
        {
            int hl = t >> 4, c4 = (t & 15) * 4;
            *(float4*)&piI[hl][c4] = *(const float4*)&d_piT[(h0 + hl) * NN + i0 + c4];
            *(float4*)&pbJ[hl][c4] = *(const float4*)&d_pbT[(h0 + hl) * NN + j0 + c4];
            *(float4*)&piJ[hl][c4] = *(const float4*)&d_piT[(h0 + hl) * NN + j0 + c4];
            *(float4*)&pbI[hl][c4] = *(const float4*)&d_pbT[(h0 + hl) * NN + i0 + c4];
        }
        __syncthreads();

#pragma unroll 8
        for (int hl = 0; hl < 32; hl++) {
            float4 pI = *(const float4*)&piI[hl][ty4];
            float4 bI = *(const float4*)&pbI[hl][ty4];
            float2 pJ = *(const float2*)&piJ[hl][tx * 2];
            float2 bJ = *(const float2*)&pbJ[hl][tx * 2];
            float wh = w_s[h0 + hl];
            float2 w2 = make_float2(wh, wh);
            float pa[4] = {pI.x, pI.y, pI.z, pI.w};
            float ba[4] = {bI.x, bI.y, bI.z, bI.w};
#pragma unroll
            for (int a = 0; a < 4; a++) {
                float2 s = f2add(make_float2(pa[a], pa[a]), bJ);
                s.x = fmaxf(s.x, 0.f); s.y = fmaxf(s.y, 0.f);
                acc1[a] = f2fma(s, w2, acc1[a]);
                float2 u2 = f2add(make_float2(ba[a], ba[a]), pJ);
                u2.x = fmaxf(u2.x, 0.f); u2.y = fmaxf(u2.y, 0.f);
                acc2[a] = f2fma(u2, w2, acc2[a]);
            }
        }
    }

    const float b2 = em_b2[0];
    __syncthreads();
    float (*ov)[68] = (float(*)[68])pool;   // [j][i], rows 16B-aligned

#pragma unroll
    for (int a = 0; a < 4; a++) {
        float v0 = 0.5f * (sigm(acc1[a].x + b2) + sigm(acc2[a].x + b2));
        float v1 = 0.5f * (sigm(acc1[a].y + b2) + sigm(acc2[a].y + b2));
        *(float2*)&out[(i0 + ty4 + a) * NN + j0 + tx * 2] = make_float2(v0, v1);
        ov[tx * 2][ty4 + a]     = v0;
        ov[tx * 2 + 1][ty4 + a] = v1;
    }
    __syncthreads();

    {
        int r = t >> 3, c8 = (t & 7) * 8;
        float4 v0 = *(const float4*)&ov[r][c8];
        float4 v1 = *(const float4*)&ov[r][c8 + 4];
        *(float4*)&out[(j0 + r) * NN + i0 + c8]     = v0;
        *(float4*)&out[(j0 + r) * NN + i0 + c8 + 4] = v1;
    }
}

// ---------------- launch ----------------
extern "C" void kernel_launch(void* const* d_in, const int* in_sizes, int n_in,
                              void* d_out, int out_size)
{
    const int o = (n_in >= 19 && in_sizes[2] == 1) ? 1 : 0;
    const float* z     = (const float*)d_in[0];
    const float* ne    = (const float*)d_in[1];
    const float* ld_w1 = (const float*)d_in[2 + o];
    const float* ld_b1 = (const float*)d_in[3 + o];
    const float* ld_g  = (const float*)d_in[4 + o];
    const float* ld_be = (const float*)d_in[5 + o];
    const float* ld_w2 = (const float*)d_in[6 + o];
    const float* ld_b2 = (const float*)d_in[7 + o];
    const float* nr_w1 = (const float*)d_in[8 + o];
    const float* nr_b1 = (const float*)d_in[9 + o];
    const float* nr_g  = (const float*)d_in[10 + o];
    const float* nr_be = (const float*)d_in[11 + o];
    const float* nr_w2 = (const float*)d_in[12 + o];
    const float* nr_b2 = (const float*)d_in[13 + o];
    const float* em_w1 = (const float*)d_in[14 + o];
    const float* em_b1 = (const float*)d_in[15 + o];
    const float* em_w2 = (const float*)d_in[16 + o];
    const float* em_b2 = (const float*)d_in[17 + o];
    float* out = (float*)d_out;

    kPre<<<GRIDP, NT>>>(z, ne, ld_w1, ld_b1, ld_g, ld_be, ld_w2, ld_b2,
                        nr_w1, nr_b1, nr_g, nr_be, nr_w2, nr_b2, em_w1, em_b1);
    kC<<<136, NT>>>(em_w2, em_b2, out);
}

// round 14
// speedup vs baseline: 1.0350x; 1.0350x over previous
#include <cuda_runtime.h>

#define HID 128
#define LAT 256
#define NN  1024
#define GRIDP 128u
#define NT   512

// ---------------- scratch (no allocations allowed) ----------------
__device__ float d_gvec[HID];
__device__ float d_w1hT[HID * HID];
__device__ float d_w2T [HID * HID];
__device__ float d_WaT [HID * HID];
__device__ float d_WbT [HID * HID];
__device__ float d_piT [HID * NN];
__device__ float d_pbT [HID * NN];

__device__ unsigned d_bar_count = 0;
__device__ unsigned d_bar_gen   = 0;
__device__ unsigned d_tp_done   = 0;   // transpose-completion flag (64 arrivals)

// CG-style grid barrier (proven correct): 128 co-resident blocks.
__device__ __forceinline__ void grid_bar() {
    __syncthreads();
    if (threadIdx.x == 0) {
        unsigned g;
        asm volatile("ld.acquire.gpu.global.u32 %0, [%1];"
                     : "=r"(g) : "l"(&d_bar_gen) : "memory");
        unsigned old, one = 1u, zero = 0u;
        asm volatile("atom.release.gpu.global.add.u32 %0, [%1], %2;"
                     : "=r"(old) : "l"(&d_bar_count), "r"(one) : "memory");
        if (old == GRIDP - 1u) {
            asm volatile("st.relaxed.gpu.global.u32 [%0], %1;"
                         :: "l"(&d_bar_count), "r"(zero) : "memory");
            asm volatile("red.release.gpu.global.add.u32 [%0], %1;"
                         :: "l"(&d_bar_gen), "r"(one) : "memory");
        } else {
            unsigned cur;
            do {
                asm volatile("ld.acquire.gpu.global.u32 %0, [%1];"
                             : "=r"(cur) : "l"(&d_bar_gen) : "memory");
            } while (cur == g);
        }
    }
    __syncthreads();
}

__device__ __forceinline__ void tp_arrive() {
    __syncthreads();                    // block's STGs ordered before release
    if (threadIdx.x == 0) {
        unsigned one = 1u;
        asm volatile("red.release.gpu.global.add.u32 [%0], %1;"
                     :: "l"(&d_tp_done), "r"(one) : "memory");
    }
}
__device__ __forceinline__ void tp_wait() {
    if (threadIdx.x == 0) {
        unsigned cur;
        do {
            asm volatile("ld.acquire.gpu.global.u32 %0, [%1];"
                         : "=r"(cur) : "l"(&d_tp_done) : "memory");
        } while (cur < 64u);
    }
    __syncthreads();
}

__device__ __forceinline__ float warp_sum(float v) {
#pragma unroll
    for (int o = 16; o; o >>= 1) v += __shfl_xor_sync(0xffffffffu, v, o);
    return v;
}

__device__ __forceinline__ float2 f2add(float2 a, float2 b) {
    unsigned long long ua = *reinterpret_cast<unsigned long long*>(&a);
    unsigned long long ub = *reinterpret_cast<unsigned long long*>(&b);
    unsigned long long ur;
    asm("add.rn.f32x2 %0, %1, %2;" : "=l"(ur) : "l"(ua), "l"(ub));
    return *reinterpret_cast<float2*>(&ur);
}
// NOTE: no max.f32x2 in PTX — packed family is add/mul/fma only. Scalar FMNMX relu.
__device__ __forceinline__ float2 f2max0(float2 a) {
    return make_float2(fmaxf(a.x, 0.f), fmaxf(a.y, 0.f));
}
__device__ __forceinline__ float2 f2fma(float2 a, float2 b, float2 c) {
    unsigned long long ua = *reinterpret_cast<unsigned long long*>(&a);
    unsigned long long ub = *reinterpret_cast<unsigned long long*>(&b);
    unsigned long long uc = *reinterpret_cast<unsigned long long*>(&c);
    unsigned long long ur;
    asm("fma.rn.f32x2 %0, %1, %2, %3;" : "=l"(ur) : "l"(ua), "l"(ub), "l"(uc));
    return *reinterpret_cast<float2*>(&ur);
}
__device__ __forceinline__ float sigm(float x) { return 1.f / (1.f + __expf(-x)); }

// ================= kernel Pre =================
__global__ __launch_bounds__(NT) void kPre(
    const float* __restrict__ z,  const float* __restrict__ ne,
    const float* __restrict__ ld_w1, const float* __restrict__ ld_b1,
    const float* __restrict__ ld_g,  const float* __restrict__ ld_be,
    const float* __restrict__ ld_w2, const float* __restrict__ ld_b2,
    const float* __restrict__ nr_w1, const float* __restrict__ nr_b1,
    const float* __restrict__ nr_g,  const float* __restrict__ nr_be,
    const float* __restrict__ nr_w2, const float* __restrict__ nr_b2,
    const float* __restrict__ em_w1, const float* __restrict__ em_b1)
{
    __shared__ float SM[6528];   // 25.5 KB
    const int t   = threadIdx.x;
    const int blk = blockIdx.x;
    const int w = t >> 5, l = t & 31;

    // ----- phase 0a: weight transposes (blocks 64..127), then flag arrive -----
    if (blk >= 64) {
        float (*s)[33] = (float(*)[33])SM;
        const int tileIdx = blk - 64;
        const int m  = tileIdx >> 4;
        const int t16 = tileIdx & 15;
        const int c0 = (t16 >> 2) * 32;
        const int k0 = (t16 & 3) * 32;
        const float* src; int stride, colOff; float* dst;
        if      (m == 0) { src = nr_w1; stride = LAT; colOff = 0;   dst = d_w1hT; }
        else if (m == 1) { src = nr_w2; stride = HID; colOff = 0;   dst = d_w2T;  }
        else if (m == 2) { src = em_w1; stride = LAT; colOff = 0;   dst = d_WaT;  }
        else             { src = em_w1; stride = LAT; colOff = HID; dst = d_WbT;  }
        const int x = t & 31, y = t >> 5;
#pragma unroll
        for (int yy = y; yy < 32; yy += 16)
            s[yy][x] = src[(k0 + yy) * stride + colOff + c0 + x];
        __syncthreads();
#pragma unroll
        for (int yy = y; yy < 32; yy += 16)
            dst[(c0 + yy) * HID + k0 + x] = s[x][yy];
        tp_arrive();
    }

    // ----- phase 0b: latent chain on block 0 -> d_gvec -----
    if (blk == 0) {
        float* z_s = SM;             // 256
        float* hA  = SM + 256;       // 256
        float* aA  = SM + 512;       // 256
        float* gA  = SM + 768;       // 128
        float* redA = SM + 896;      // 8
        float* redB = SM + 904;      // 8

        if (t < 64) ((float4*)z_s)[t] = ((const float4*)z)[t];
        __syncthreads();
        const float4* zf4 = (const float4*)z_s;

        for (int m0 = 0; m0 < 16; m0 += 4) {
            float p[4];
#pragma unroll
            for (int k = 0; k < 4; k++) {
                int r = (m0 + k) * 16 + w;
                const float4* wr = (const float4*)&ld_w1[r * LAT];
                float4 A = wr[l], B = wr[l + 32];
                float4 za = zf4[l], zb = zf4[l + 32];
                p[k] = A.x*za.x + A.y*za.y + A.z*za.z + A.w*za.w
                     + B.x*zb.x + B.y*zb.y + B.z*zb.z + B.w*zb.w;
            }
#pragma unroll
            for (int o = 16; o; o >>= 1) {
                p[0] += __shfl_xor_sync(0xffffffffu, p[0], o);
                p[1] += __shfl_xor_sync(0xffffffffu, p[1], o);
                p[2] += __shfl_xor_sync(0xffffffffu, p[2], o);
                p[3] += __shfl_xor_sync(0xffffffffu, p[3], o);
            }
            if (l == 0) {
#pragma unroll
                for (int k = 0; k < 4; k++) {
                    int r = (m0 + k) * 16 + w;
                    hA[r] = p[k] + ld_b1[r];
                }
            }
        }
        __syncthreads();

        {
            float x = (t < 256) ? hA[t] : 0.f;
            float s1 = warp_sum(x), s2 = warp_sum(x * x);
            if (l == 0 && w < 8) { redA[w] = s1; redB[w] = s2; }
            __syncthreads();
            float tot = 0.f, tot2 = 0.f;
#pragma unroll
            for (int i = 0; i < 8; i++) { tot += redA[i]; tot2 += redB[i]; }
            float mu = tot * (1.f / 256.f);
            float var = tot2 * (1.f / 256.f) - mu * mu;
            float rs = rsqrtf(var + 1e-5f);
            if (t < 256) aA[t] = fmaxf((x - mu) * rs * ld_g[t] + ld_be[t], 0.f);
        }
        __syncthreads();
        const float4* af4 = (const float4*)aA;

        for (int m0 = 0; m0 < 8; m0 += 4) {
            float p[4];
#pragma unroll
            for (int k = 0; k < 4; k++) {
                int r = (m0 + k) * 16 + w;
                const float4* wr = (const float4*)&ld_w2[r * LAT];
                float4 A = wr[l], B = wr[l + 32];
                float4 za = af4[l], zb = af4[l + 32];
                p[k] = A.x*za.x + A.y*za.y + A.z*za.z + A.w*za.w
                     + B.x*zb.x + B.y*zb.y + B.z*zb.z + B.w*zb.w;
            }
#pragma unroll
            for (int o = 16; o; o >>= 1) {
                p[0] += __shfl_xor_sync(0xffffffffu, p[0], o);
                p[1] += __shfl_xor_sync(0xffffffffu, p[1], o);
                p[2] += __shfl_xor_sync(0xffffffffu, p[2], o);
                p[3] += __shfl_xor_sync(0xffffffffu, p[3], o);
            }
            if (l == 0) {
#pragma unroll
                for (int k = 0; k < 4; k++) {
                    int r = (m0 + k) * 16 + w;
                    gA[r] = p[k] + ld_b2[r];
                }
            }
        }
        __syncthreads();
        const float4* gf4 = (const float4*)gA;

        for (int m0 = 0; m0 < 8; m0 += 4) {
            float p[4];
#pragma unroll
            for (int k = 0; k < 4; k++) {
                int r = (m0 + k) * 16 + w;
                const float4* wr = (const float4*)&nr_w1[r * LAT + HID];
                float4 A = wr[l];
                float4 ga = gf4[l];
                p[k] = A.x*ga.x + A.y*ga.y + A.z*ga.z + A.w*ga.w;
            }
#pragma unroll
            for (int o = 16; o; o >>= 1) {
                p[0] += __shfl_xor_sync(0xffffffffu, p[0], o);
                p[1] += __shfl_xor_sync(0xffffffffu, p[1], o);
                p[2] += __shfl_xor_sync(0xffffffffu, p[2], o);
                p[3] += __shfl_xor_sync(0xffffffffu, p[3], o);
            }
            if (l == 0) {
#pragma unroll
                for (int k = 0; k < 4; k++) {
                    int r = (m0 + k) * 16 + w;
                    d_gvec[r] = p[k] + nr_b1[r];
                }
            }
        }
        __syncthreads();
    }

    // ----- phase B: node MLP (pre-barrier: GEMV1 without gvec bias) -----
    {
        float* A  = SM;              // 1024: ne, later nf
        float* B  = SM + 1024;       // 1024: t1/LN, later pi
        float* WT = SM + 2048;       // 4096: weight tile [32 c][128 j]
        float* red1 = SM + 6144;     // 16
        float* red2 = SM + 6160;     // 16
        const int i0 = (blk == 0) ? 127 * 8 : (blk - 1) * 8;
        const int r  = t >> 6;       // node 0..7
        const int u  = t & 63;
        const int j2 = u * 2;
        const int wh2 = u >> 5;
        const int ti8 = t * 8;

        // fill A with node embeddings (after any SM use above)
        __syncthreads();
        for (int q = t; q < 8 * HID; q += NT) A[q] = ne[i0 * HID + q];

        tp_wait();                   // w1hT..WbT visible (block 0: already past)

        // tile prefetch machinery: 16 tiles, reg double-buffer
        const float* bases[4] = { d_w1hT, d_w2T, d_WaT, d_WbT };
        float4 pf0, pf1;
        {
            const float* p = bases[0] + ti8;
            pf0 = *(const float4*)p; pf1 = *(const float4*)(p + 4);
        }
        int pidx = 1;
#define STAGE_TILE()                                                        \
        do {                                                                \
            __syncthreads();                                                \
            *(float4*)&WT[ti8] = pf0; *(float4*)&WT[ti8 + 4] = pf1;         \
            if (pidx < 16) {                                                \
                const float* p = bases[pidx >> 2] + (pidx & 3) * 4096 + ti8;\
                pf0 = *(const float4*)p; pf1 = *(const float4*)(p + 4);     \
            }                                                               \
            pidx++;                                                         \
            __syncthreads();                                                \
        } while (0)

        // GEMV1: t1 = ne @ w1hT (NO gvec bias — folded into LN)
        float2 acc = make_float2(0.f, 0.f);
#pragma unroll
        for (int ct = 0; ct < 4; ct++) {
            STAGE_TILE();
#pragma unroll
            for (int c4 = 0; c4 < 32; c4 += 4) {
                float4 nv = *(const float4*)&A[r * HID + ct * 32 + c4];
                acc = f2fma(make_float2(nv.x, nv.x), *(const float2*)&WT[(c4 + 0) * HID + j2], acc);
                acc = f2fma(make_float2(nv.y, nv.y), *(const float2*)&WT[(c4 + 1) * HID + j2], acc);
                acc = f2fma(make_float2(nv.z, nv.z), *(const float2*)&WT[(c4 + 2) * HID + j2], acc);
                acc = f2fma(make_float2(nv.w, nv.w), *(const float2*)&WT[(c4 + 3) * HID + j2], acc);
            }
        }
        *(float2*)&B[r * HID + j2] = acc;

        grid_bar();                  // waits for chain (d_gvec) + all GEMV1 t1

        if (blk == 0 && t == 0) {    // reset transpose flag for next graph replay
            unsigned zero = 0u;
            asm volatile("st.relaxed.gpu.global.u32 [%0], %1;"
                         :: "l"(&d_tp_done), "r"(zero) : "memory");
        }

        // LayerNorm(128) + relu, gvec bias folded in
        {
            float x0 = B[r * HID + u]      + d_gvec[u];
            float x1 = B[r * HID + u + 64] + d_gvec[u + 64];
            float s1 = warp_sum(x0 + x1);
            float s2 = warp_sum(x0 * x0 + x1 * x1);
            if (l == 0) { red1[r * 2 + wh2] = s1; red2[r * 2 + wh2] = s2; }
            __syncthreads();
            float mu  = (red1[r * 2] + red1[r * 2 + 1]) * (1.f / 128.f);
            float var = (red2[r * 2] + red2[r * 2 + 1]) * (1.f / 128.f) - mu * mu;
            float rs = rsqrtf(var + 1e-5f);
            B[r * HID + u]      = fmaxf((x0 - mu) * rs * nr_g[u]      + nr_be[u],      0.f);
            B[r * HID + u + 64] = fmaxf((x1 - mu) * rs * nr_g[u + 64] + nr_be[u + 64], 0.f);
        }

        // GEMV2: nf = a @ w2T + b2 -> A (overwrites ne after its last read)
        float2 nf = *(const float2*)&nr_b2[j2];
        float2 nf_parts[4];
#pragma unroll
        for (int ct = 0; ct < 4; ct++) {
            STAGE_TILE();
            float2 pp = (ct == 0) ? nf : make_float2(0.f, 0.f);
#pragma unroll
            for (int c4 = 0; c4 < 32; c4 += 4) {
                float4 av = *(const float4*)&B[r * HID + ct * 32 + c4];
                pp = f2fma(make_float2(av.x, av.x), *(const float2*)&WT[(c4 + 0) * HID + j2], pp);
                pp = f2fma(make_float2(av.y, av.y), *(const float2*)&WT[(c4 + 1) * HID + j2], pp);
                pp = f2fma(make_float2(av.z, av.z), *(const float2*)&WT[(c4 + 2) * HID + j2], pp);
                pp = f2fma(make_float2(av.w, av.w), *(const float2*)&WT[(c4 + 3) * HID + j2], pp);
            }
            nf_parts[ct] = pp;
        }
        nf = f2add(f2add(nf_parts[0], nf_parts[1]), f2add(nf_parts[2], nf_parts[3]));
        __syncthreads();             // all reads of A (ne) done before overwrite
        *(float2*)&A[r * HID + j2] = nf;

        // GEMV3: pi = nf @ WaT -> B
        float2 pi = make_float2(0.f, 0.f);
#pragma unroll
        for (int ct = 0; ct < 4; ct++) {
            STAGE_TILE();
#pragma unroll
            for (int c4 = 0; c4 < 32; c4 += 4) {
                float4 fv = *(const float4*)&A[r * HID + ct * 32 + c4];
                pi = f2fma(make_float2(fv.x, fv.x), *(const float2*)&WT[(c4 + 0) * HID + j2], pi);
                pi = f2fma(make_float2(fv.y, fv.y), *(const float2*)&WT[(c4 + 1) * HID + j2], pi);
                pi = f2fma(make_float2(fv.z, fv.z), *(const float2*)&WT[(c4 + 2) * HID + j2], pi);
                pi = f2fma(make_float2(fv.w, fv.w), *(const float2*)&WT[(c4 + 3) * HID + j2], pi);
            }
        }
        __syncthreads();             // all reads of B (LN activations) done
        *(float2*)&B[r * HID + j2] = pi;

        // GEMV4: pb = nf @ WbT + em_b1 -> parked in WT after last tile
        float2 pb = *(const float2*)&em_b1[j2];
#pragma unroll
        for (int ct = 0; ct < 4; ct++) {
            STAGE_TILE();
#pragma unroll
            for (int c4 = 0; c4 < 32; c4 += 4) {
                float4 fv = *(const float4*)&A[r * HID + ct * 32 + c4];
                pb = f2fma(make_float2(fv.x, fv.x), *(const float2*)&WT[(c4 + 0) * HID + j2], pb);
                pb = f2fma(make_float2(fv.y, fv.y), *(const float2*)&WT[(c4 + 1) * HID + j2], pb);
                pb = f2fma(make_float2(fv.z, fv.z), *(const float2*)&WT[(c4 + 2) * HID + j2], pb);
                pb = f2fma(make_float2(fv.w, fv.w), *(const float2*)&WT[(c4 + 3) * HID + j2], pb);
            }
        }
        __syncthreads();             // all WT reads done
        *(float2*)&WT[r * HID + j2] = pb;
        __syncthreads();
#undef STAGE_TILE

        // transposed writeback
        if (t < HID) {
            const int j = t;
            float4 lo = make_float4(B[0*HID+j], B[1*HID+j], B[2*HID+j], B[3*HID+j]);
            float4 hi = make_float4(B[4*HID+j], B[5*HID+j], B[6*HID+j], B[7*HID+j]);
            *(float4*)&d_piT[j * NN + i0]     = lo;
            *(float4*)&d_piT[j * NN + i0 + 4] = hi;
            float4 lo2 = make_float4(WT[0*HID+j], WT[1*HID+j], WT[2*HID+j], WT[3*HID+j]);
            float4 hi2 = make_float4(WT[4*HID+j], WT[5*HID+j], WT[6*HID+j], WT[7*HID+j]);
            *(float4*)&d_pbT[j * NN + i0]     = lo2;
            *(float4*)&d_pbT[j * NN + i0 + 4] = hi2;
        }
    }
}

// ================= kernel C: edge scores + fused symmetrize =================
__global__ __launch_bounds__(NT) void kC(
    const float* __restrict__ em_w2, const float* __restrict__ em_b2,
    float* __restrict__ out)
{
    __shared__ float SM[8448];
    float* pool = SM;
    float* w_s  = SM + 8192;
    float (*piI)[64] = (float(*)[64])(pool);
    float (*pbJ)[64] = (float(*)[64])(pool + 2048);
    float (*piJ)[64] = (float(*)[64])(pool + 4096);
    float (*pbI)[64] = (float(*)[64])(pool + 6144);

    const int t = threadIdx.x;
    const int tx = t & 31;
    const int ty = t >> 5;
    const int ty4 = ty * 4;

    int b = blockIdx.x, bi = 0;
    while (b >= (16 - bi)) { b -= (16 - bi); bi++; }
    const int bj = bi + b;
    const int i0 = bi * 64, j0 = bj * 64;

    if (t < HID) w_s[t] = em_w2[t];

    float2 acc1[4] = {};
    float2 acc2[4] = {};

#pragma unroll
    for (int ch = 0; ch < 4; ch++) {
        __syncthreads();
        const int h0 = ch * 32;
        {
            int hl = t >> 4, c4 = (t & 15) * 4;
            *(float4*)&piI[hl][c4] = *(const float4*)&d_piT[(h0 + hl) * NN + i0 + c4];
            *(float4*)&pbJ[hl][c4] = *(const float4*)&d_pbT[(h0 + hl) * NN + j0 + c4];
            *(float4*)&piJ[hl][c4] = *(const float4*)&d_piT[(h0 + hl) * NN + j0 + c4];
            *(float4*)&pbI[hl][c4] = *(const float4*)&d_pbT[(h0 + hl) * NN + i0 + c4];
        }
        __syncthreads();

#pragma unroll 8
        for (int hl = 0; hl < 32; hl++) {
            float4 pI = *(const float4*)&piI[hl][ty4];
            float4 bI = *(const float4*)&pbI[hl][ty4];
            float2 pJ = *(const float2*)&piJ[hl][tx * 2];
            float2 bJ = *(const float2*)&pbJ[hl][tx * 2];
            float wh = w_s[h0 + hl];
            float2 w2 = make_float2(wh, wh);
            float pa[4] = {pI.x, pI.y, pI.z, pI.w};
            float ba[4] = {bI.x, bI.y, bI.z, bI.w};
#pragma unroll
            for (int a = 0; a < 4; a++) {
                float2 s = f2max0(f2add(make_float2(pa[a], pa[a]), bJ));
                acc1[a] = f2fma(s, w2, acc1[a]);
                float2 u2 = f2max0(f2add(make_float2(ba[a], ba[a]), pJ));
                acc2[a] = f2fma(u2, w2, acc2[a]);
            }
        }
    }

    const float b2 = em_b2[0];
    __syncthreads();
    float (*ov)[68] = (float(*)[68])pool;   // [j][i], rows 16B-aligned

#pragma unroll
    for (int a = 0; a < 4; a++) {
        float v0 = 0.5f * (sigm(acc1[a].x + b2) + sigm(acc2[a].x + b2));
        float v1 = 0.5f * (sigm(acc1[a].y + b2) + sigm(acc2[a].y + b2));
        *(float2*)&out[(i0 + ty4 + a) * NN + j0 + tx * 2] = make_float2(v0, v1);
        ov[tx * 2][ty4 + a]     = v0;
        ov[tx * 2 + 1][ty4 + a] = v1;
    }
    __syncthreads();

    {
        int r = t >> 3, c8 = (t & 7) * 8;
        float4 v0 = *(const float4*)&ov[r][c8];
        float4 v1 = *(const float4*)&ov[r][c8 + 4];
        *(float4*)&out[(j0 + r) * NN + i0 + c8]     = v0;
        *(float4*)&out[(j0 + r) * NN + i0 + c8 + 4] = v1;
    }
}

// ---------------- launch ----------------
extern "C" void kernel_launch(void* const* d_in, const int* in_sizes, int n_in,
                              void* d_out, int out_size)
{
    const int o = (n_in >= 19 && in_sizes[2] == 1) ? 1 : 0;
    const float* z     = (const float*)d_in[0];
    const float* ne    = (const float*)d_in[1];
    const float* ld_w1 = (const float*)d_in[2 + o];
    const float* ld_b1 = (const float*)d_in[3 + o];
    const float* ld_g  = (const float*)d_in[4 + o];
    const float* ld_be = (const float*)d_in[5 + o];
    const float* ld_w2 = (const float*)d_in[6 + o];
    const float* ld_b2 = (const float*)d_in[7 + o];
    const float* nr_w1 = (const float*)d_in[8 + o];
    const float* nr_b1 = (const float*)d_in[9 + o];
    const float* nr_g  = (const float*)d_in[10 + o];
    const float* nr_be = (const float*)d_in[11 + o];
    const float* nr_w2 = (const float*)d_in[12 + o];
    const float* nr_b2 = (const float*)d_in[13 + o];
    const float* em_w1 = (const float*)d_in[14 + o];
    const float* em_b1 = (const float*)d_in[15 + o];
    const float* em_w2 = (const float*)d_in[16 + o];
    const float* em_b2 = (const float*)d_in[17 + o];
    float* out = (float*)d_out;

    kPre<<<GRIDP, NT>>>(z, ne, ld_w1, ld_b1, ld_g, ld_be, ld_w2, ld_b2,
                        nr_w1, nr_b1, nr_g, nr_be, nr_w2, nr_b2, em_w1, em_b1);
    kC<<<136, NT>>>(em_w2, em_b2, out);
}